// round 3
// baseline (speedup 1.0000x reference)
#include <cuda_runtime.h>
#include <cuda.h>
#include <cuda_bf16.h>
#include <cstdint>

// ===================== problem constants =====================
#define M_DIM 8192
#define K_DIM 4096
#define N_DIM 11008

#define TILE_M 128
#define TILE_N 128
#define KC 64                    // K per stage (64 bf16 = 128B = one SW128 row)
#define STAGES 4
#define MT (M_DIM / TILE_M)      // 64
#define NT (N_DIM / TILE_N)      // 86
#define GROUP_M 8
#define NITER (K_DIM / KC)       // 64

#define STAGE_BYTES 49152        // A_hi 16K + A_lo 16K + B 16K
// CRITICAL: stage data must be 1024-byte aligned — TMA's SW128 swizzle keys off
// ABSOLUTE smem address bits [9:7]; a 128-byte-offset base shifts the pattern.
#define DATA_OFF 1024
#define SMEM_TOTAL (DATA_OFF + STAGES * STAGE_BYTES)   // 197632

// ===================== scratch (device globals; no allocs allowed) =====================
__device__ __align__(256) __nv_bfloat16 g_Ahi[(size_t)M_DIM * K_DIM];
__device__ __align__(256) __nv_bfloat16 g_Alo[(size_t)M_DIM * K_DIM];
__device__ __align__(256) __nv_bfloat16 g_Wq [(size_t)N_DIM * K_DIM];

// ===================== PTX helpers (ALL plain-sm_103-safe) =====================
__device__ __forceinline__ uint32_t smem_u32(const void* p) {
    uint32_t a;
    asm("{ .reg .u64 t; cvta.to.shared.u64 t, %1; cvt.u32.u64 %0, t; }" : "=r"(a) : "l"(p));
    return a;
}

#define MBAR_INIT(addr, cnt) \
    asm volatile("mbarrier.init.shared.b64 [%0], %1;" :: "r"(addr), "r"(cnt) : "memory")

#define MBAR_ARRIVE(addr) \
    asm volatile("mbarrier.arrive.shared.b64 _, [%0];" :: "r"(addr) : "memory")

#define MBAR_EXPECT_TX(addr, bytes) \
    asm volatile("mbarrier.arrive.expect_tx.shared.b64 _, [%0], %1;" :: "r"(addr), "r"(bytes) : "memory")

#define MBAR_WAIT(addr, phase) do {                                              \
    asm volatile("{\n\t.reg .pred P;\n\t"                                        \
        "W_%=:\n\t"                                                              \
        "mbarrier.try_wait.parity.shared.b64 P, [%0], %1, 0x989680;\n\t"         \
        "@!P bra W_%=;\n\t}"                                                     \
        :: "r"(addr), "r"(phase) : "memory");                                    \
} while (0)

#define TMA_LOAD_2D(dst, map, cx, cy, mbar) \
    asm volatile("cp.async.bulk.tensor.2d.shared::cta.global.tile.mbarrier::complete_tx::bytes " \
                 "[%0], [%1, {%2, %3}], [%4];" \
                 :: "r"(dst), "l"(map), "r"(cx), "r"(cy), "r"(mbar) : "memory")

#define LDMATRIX_X4(r, addr) \
    asm volatile("ldmatrix.sync.aligned.m8n8.x4.shared.b16 {%0, %1, %2, %3}, [%4];" \
                 : "=r"((r)[0]), "=r"((r)[1]), "=r"((r)[2]), "=r"((r)[3]) : "r"(addr))

#define MMA_BF16(d, a, b0, b1) \
    asm volatile("mma.sync.aligned.m16n8k16.row.col.f32.bf16.bf16.f32 " \
                 "{%0, %1, %2, %3}, {%4, %5, %6, %7}, {%8, %9}, {%0, %1, %2, %3};" \
                 : "+f"((d)[0]), "+f"((d)[1]), "+f"((d)[2]), "+f"((d)[3]) \
                 : "r"((a)[0]), "r"((a)[1]), "r"((a)[2]), "r"((a)[3]), "r"(b0), "r"(b1))

// ===================== prep kernels =====================
// x (fp32) -> x_hi (bf16) + x_lo (bf16 residual): hi+lo reproduces x to ~2^-17.
__global__ void convert_x_kernel(const float* __restrict__ x,
                                 __nv_bfloat16* __restrict__ hi,
                                 __nv_bfloat16* __restrict__ lo, int n4) {
    int i = blockIdx.x * blockDim.x + threadIdx.x;
    if (i >= n4) return;
    float4 v = reinterpret_cast<const float4*>(x)[i];
    __nv_bfloat16 h0 = __float2bfloat16(v.x);
    __nv_bfloat16 h1 = __float2bfloat16(v.y);
    __nv_bfloat16 h2 = __float2bfloat16(v.z);
    __nv_bfloat16 h3 = __float2bfloat16(v.w);
    __nv_bfloat16 l0 = __float2bfloat16(v.x - __bfloat162float(h0));
    __nv_bfloat16 l1 = __float2bfloat16(v.y - __bfloat162float(h1));
    __nv_bfloat16 l2 = __float2bfloat16(v.z - __bfloat162float(h2));
    __nv_bfloat16 l3 = __float2bfloat16(v.w - __bfloat162float(h3));
    __nv_bfloat162 ha = __halves2bfloat162(h0, h1), hb = __halves2bfloat162(h2, h3);
    __nv_bfloat162 la = __halves2bfloat162(l0, l1), lb = __halves2bfloat162(l2, l3);
    uint2 hu, lu;
    hu.x = *reinterpret_cast<uint32_t*>(&ha); hu.y = *reinterpret_cast<uint32_t*>(&hb);
    lu.x = *reinterpret_cast<uint32_t*>(&la); lu.y = *reinterpret_cast<uint32_t*>(&lb);
    reinterpret_cast<uint2*>(hi)[i] = hu;
    reinterpret_cast<uint2*>(lo)[i] = lu;
}

// int32 q -> bf16 (q - zp). Exact: integers in [-128,127] are exact bf16.
__global__ void convert_w_kernel(const int* __restrict__ q,
                                 const float* __restrict__ zp_ptr,
                                 __nv_bfloat16* __restrict__ w, int n4) {
    int i = blockIdx.x * blockDim.x + threadIdx.x;
    if (i >= n4) return;
    float zp = __ldg(zp_ptr);
    int4 v = reinterpret_cast<const int4*>(q)[i];
    __nv_bfloat16 w0 = __float2bfloat16((float)v.x - zp);
    __nv_bfloat16 w1 = __float2bfloat16((float)v.y - zp);
    __nv_bfloat16 w2 = __float2bfloat16((float)v.z - zp);
    __nv_bfloat16 w3 = __float2bfloat16((float)v.w - zp);
    __nv_bfloat162 a = __halves2bfloat162(w0, w1), b = __halves2bfloat162(w2, w3);
    uint2 u;
    u.x = *reinterpret_cast<uint32_t*>(&a); u.y = *reinterpret_cast<uint32_t*>(&b);
    reinterpret_cast<uint2*>(w)[i] = u;
}

// ===================== GEMM kernel =====================
// 288 threads: warps 0-7 compute (2x4 -> warp tile 64x32), warp 8 lane 0 = TMA producer.
// Barriers: full[s] @ sb+16s (count 1, tx), empty[s] @ sb+16s+8 (count 8).
__global__ void __launch_bounds__(288, 1) gemm_kernel(
    const __grid_constant__ CUtensorMap tma_ahi,
    const __grid_constant__ CUtensorMap tma_alo,
    const __grid_constant__ CUtensorMap tma_b,
    const float* __restrict__ scale_ptr,
    const float* __restrict__ bias,
    float* __restrict__ out)
{
    extern __shared__ __align__(1024) char smem[];
    const uint32_t sb = smem_u32(smem);
    const int tid  = threadIdx.x;
    const int wid  = tid >> 5;
    const int lane = tid & 31;

    // tile rasterization: groups of GROUP_M m-tiles iterate n fastest (L2 reuse)
    int bid   = blockIdx.x;
    int group = bid / (GROUP_M * NT);
    int r     = bid % (GROUP_M * NT);
    int tm    = group * GROUP_M + (r % GROUP_M);
    int tn    = r / GROUP_M;

    if (tid == 0) {
        #pragma unroll
        for (int s = 0; s < STAGES; s++) {
            MBAR_INIT(sb + 16 * s, 1);        // full
            MBAR_INIT(sb + 16 * s + 8, 8);    // empty (8 compute warps)
        }
    }
    __syncthreads();

    if (wid == 8) {
        // ---------------- producer ----------------
        if (lane == 0) {
            int st = 0, ph = 1;   // fresh barrier: parity-1 empty-wait passes immediately
            #pragma unroll 1
            for (int it = 0; it < NITER; it++) {
                MBAR_WAIT(sb + 16 * st + 8, ph);
                uint32_t full = sb + 16 * st;
                uint32_t base = sb + DATA_OFF + st * STAGE_BYTES;
                MBAR_EXPECT_TX(full, STAGE_BYTES);
                int kx = it * KC;
                TMA_LOAD_2D(base,         &tma_ahi, kx, tm * TILE_M, full);
                TMA_LOAD_2D(base + 16384, &tma_alo, kx, tm * TILE_M, full);
                TMA_LOAD_2D(base + 32768, &tma_b,   kx, tn * TILE_N, full);
                if (++st == STAGES) { st = 0; ph ^= 1; }
            }
        }
        return;
    }

    // ---------------- compute warps ----------------
    const int wm = wid & 1;    // 0..1 -> m offset 64*wm
    const int wn = wid >> 1;   // 0..3 -> n offset 32*wn

    float acc[4][4][4];
    #pragma unroll
    for (int mi = 0; mi < 4; mi++)
        #pragma unroll
        for (int ni = 0; ni < 4; ni++)
            #pragma unroll
            for (int j = 0; j < 4; j++) acc[mi][ni][j] = 0.f;

    // per-lane ldmatrix geometry
    const int a_r  = lane & 15;             // row within m16 tile
    const int a_kl = (lane >> 4) << 3;      // k offset 0 / 8
    const int b_n  = (lane & 7) + ((lane >> 4) << 3);  // n within n16 tile
    const int b_kl = ((lane >> 3) & 1) << 3;           // k offset 0 / 8

    int st = 0, ph = 0;
    #pragma unroll 1
    for (int it = 0; it < NITER; it++) {
        MBAR_WAIT(sb + 16 * st, ph);
        const uint32_t aHiB = sb + DATA_OFF + st * STAGE_BYTES;
        const uint32_t aLoB = aHiB + 16384;
        const uint32_t bB   = aHiB + 32768;

        #pragma unroll
        for (int ks = 0; ks < 4; ks++) {
            uint32_t bf[2][4];
            #pragma unroll
            for (int nb = 0; nb < 2; nb++) {
                int n  = wn * 32 + nb * 16 + b_n;
                int kb = (ks * 16 + b_kl) * 2;
                uint32_t off = (uint32_t)(n * 128) + ((uint32_t)kb ^ (uint32_t)((n & 7) << 4));
                LDMATRIX_X4(bf[nb], bB + off);
            }
            uint32_t ah[4][4], al[4][4];
            #pragma unroll
            for (int mi = 0; mi < 4; mi++) {
                int m  = wm * 64 + mi * 16 + a_r;
                int kb = (ks * 16 + a_kl) * 2;
                uint32_t off = (uint32_t)(m * 128) + ((uint32_t)kb ^ (uint32_t)((m & 7) << 4));
                LDMATRIX_X4(ah[mi], aHiB + off);
                LDMATRIX_X4(al[mi], aLoB + off);
            }
            #pragma unroll
            for (int mi = 0; mi < 4; mi++)
                #pragma unroll
                for (int ni = 0; ni < 4; ni++) {
                    uint32_t b0 = bf[ni >> 1][(ni & 1) * 2];
                    uint32_t b1 = bf[ni >> 1][(ni & 1) * 2 + 1];
                    MMA_BF16(acc[mi][ni], ah[mi], b0, b1);
                    MMA_BF16(acc[mi][ni], al[mi], b0, b1);
                }
        }
        if (lane == 0) MBAR_ARRIVE(sb + 16 * st + 8);
        if (++st == STAGES) { st = 0; ph ^= 1; }
    }

    // ---------------- epilogue: out = scale*acc + bias ----------------
    const float sc = __ldg(scale_ptr);
    const int m0 = tm * TILE_M + wm * 64 + (lane >> 2);
    const int n0 = tn * TILE_N + wn * 32 + (lane & 3) * 2;
    #pragma unroll
    for (int mi = 0; mi < 4; mi++) {
        #pragma unroll
        for (int ni = 0; ni < 4; ni++) {
            int row = m0 + mi * 16;
            int col = n0 + ni * 8;
            float2 bv = *reinterpret_cast<const float2*>(bias + col);
            float2 o0, o1;
            o0.x = acc[mi][ni][0] * sc + bv.x;
            o0.y = acc[mi][ni][1] * sc + bv.y;
            o1.x = acc[mi][ni][2] * sc + bv.x;
            o1.y = acc[mi][ni][3] * sc + bv.y;
            *reinterpret_cast<float2*>(out + (size_t)row * N_DIM + col)       = o0;
            *reinterpret_cast<float2*>(out + (size_t)(row + 8) * N_DIM + col) = o1;
        }
    }
}

// ===================== host =====================
typedef CUresult (*PFN_encodeTiled)(CUtensorMap*, CUtensorMapDataType, cuuint32_t, void*,
                                    const cuuint64_t*, const cuuint64_t*, const cuuint32_t*,
                                    const cuuint32_t*, CUtensorMapInterleave, CUtensorMapSwizzle,
                                    CUtensorMapL2promotion, CUtensorMapFloatOOBfill);

static void make_map_2d(PFN_encodeTiled enc, CUtensorMap* m, void* ptr,
                        uint64_t d0, uint64_t d1, uint32_t b0, uint32_t b1) {
    cuuint64_t dims[2]    = {d0, d1};
    cuuint64_t strides[1] = {d0 * sizeof(__nv_bfloat16)};
    cuuint32_t box[2]     = {b0, b1};
    cuuint32_t es[2]      = {1, 1};
    enc(m, CU_TENSOR_MAP_DATA_TYPE_BFLOAT16, 2, ptr, dims, strides, box, es,
        CU_TENSOR_MAP_INTERLEAVE_NONE, CU_TENSOR_MAP_SWIZZLE_128B,
        CU_TENSOR_MAP_L2_PROMOTION_L2_128B, CU_TENSOR_MAP_FLOAT_OOB_FILL_NONE);
}

extern "C" void kernel_launch(void* const* d_in, const int* in_sizes, int n_in,
                              void* d_out, int out_size) {
    const float* x     = (const float*)d_in[0];
    const int*   qw    = (const int*)d_in[1];
    const float* scale = (const float*)d_in[2];
    const float* zp    = (const float*)d_in[3];
    const float* bias  = (const float*)d_in[4];
    float*       out   = (float*)d_out;

    void *pAhi = nullptr, *pAlo = nullptr, *pW = nullptr;
    cudaGetSymbolAddress(&pAhi, g_Ahi);
    cudaGetSymbolAddress(&pAlo, g_Alo);
    cudaGetSymbolAddress(&pW,  g_Wq);

    PFN_encodeTiled enc = nullptr;
    cudaDriverEntryPointQueryResult qr;
    cudaGetDriverEntryPointByVersion("cuTensorMapEncodeTiled", (void**)&enc, 12000u,
                                     cudaEnableDefault, &qr);
    if (!enc) return;

    CUtensorMap mAhi, mAlo, mW;
    make_map_2d(enc, &mAhi, pAhi, K_DIM, M_DIM, KC, TILE_M);
    make_map_2d(enc, &mAlo, pAlo, K_DIM, M_DIM, KC, TILE_M);
    make_map_2d(enc, &mW,   pW,  K_DIM, N_DIM, KC, TILE_N);

    cudaFuncSetAttribute(gemm_kernel, cudaFuncAttributeMaxDynamicSharedMemorySize, SMEM_TOTAL);

    int n4x = (M_DIM * K_DIM) / 4;
    int n4w = (N_DIM * K_DIM) / 4;
    convert_x_kernel<<<(n4x + 255) / 256, 256>>>(x, (__nv_bfloat16*)pAhi, (__nv_bfloat16*)pAlo, n4x);
    convert_w_kernel<<<(n4w + 255) / 256, 256>>>(qw, zp, (__nv_bfloat16*)pW, n4w);

    gemm_kernel<<<MT * NT, 288, SMEM_TOTAL>>>(mAhi, mAlo, mW, scale, bias, out);
}